// round 5
// baseline (speedup 1.0000x reference)
#include <cuda_runtime.h>
#include <cstdint>
#include <cstddef>

#define BB 32
#define SS 48
#define VV 32000
#define EE 512
#define HH 512
#define GG 2048

// ---------------- persistent device state ----------------
__device__ __align__(16) float d_x[BB*EE];
__device__ __align__(16) float d_h[BB*HH];
__device__ __align__(16) float d_c[BB*HH];
__device__ __align__(16) float d_gates[BB*GG];
__device__ __align__(16) float d_logits[BB*VV];
__device__ __align__(16) unsigned long long d_h2h[2*HH*8];   // half-major pair-transposed h
__device__ float d_pval[BB*8];
__device__ int   d_pidx[BB*8];
__device__ float d_psum[BB*8];
__device__ int   d_active[BB];
__device__ uint2 d_keys[SS];

// ---------------- threefry2x32 (exact JAX algorithm, 20 rounds) ----------------
__device__ __forceinline__ uint2 tf2x32(unsigned k0, unsigned k1, unsigned x0, unsigned x1){
  unsigned k2 = 0x1BD11BDAu ^ k0 ^ k1;
  x0 += k0; x1 += k1;
#define TFRND(R) { x0 += x1; x1 = (x1 << (R)) | (x1 >> (32-(R))); x1 ^= x0; }
  TFRND(13) TFRND(15) TFRND(26) TFRND(6)
  x0 += k1; x1 += k2 + 1u;
  TFRND(17) TFRND(29) TFRND(16) TFRND(24)
  x0 += k2; x1 += k0 + 2u;
  TFRND(13) TFRND(15) TFRND(26) TFRND(6)
  x0 += k0; x1 += k1 + 3u;
  TFRND(17) TFRND(29) TFRND(16) TFRND(24)
  x0 += k1; x1 += k2 + 4u;
  TFRND(13) TFRND(15) TFRND(26) TFRND(6)
  x0 += k2; x1 += k0 + 5u;
#undef TFRND
  return make_uint2(x0, x1);
}

// ---------------- accurate logf (cephes-style, ~1 ulp; immune to fast-math) ----------------
__device__ __forceinline__ float acc_logf(float x){
  unsigned ix = __float_as_uint(x);
  unsigned off = ix + (0x3f800000u - 0x3f3504f3u);
  int k = ((int)(off >> 23)) - 127;
  unsigned mx = (off & 0x007fffffu) + 0x3f3504f3u;
  float f = __uint_as_float(mx) - 1.0f;
  float z = f * f;
  float p =              7.0376836292e-2f;
  p = fmaf(p, f, -1.1514610310e-1f);
  p = fmaf(p, f,  1.1676998740e-1f);
  p = fmaf(p, f, -1.2420140846e-1f);
  p = fmaf(p, f,  1.4249322787e-1f);
  p = fmaf(p, f, -1.6668057665e-1f);
  p = fmaf(p, f,  2.0000714765e-1f);
  p = fmaf(p, f, -2.4999993993e-1f);
  p = fmaf(p, f,  3.3333331174e-1f);
  float y = f * z * p;
  y = fmaf(-0.5f, z, y);
  float r = fmaf((float)k, -2.12194440e-4f, y);
  r = f + r;
  r = fmaf((float)k, 0.693359375f, r);
  return r;
}

__device__ __forceinline__ float gumbel_bits(unsigned bits){
  float f = __uint_as_float((bits >> 9) | 0x3f800000u) - 1.0f;
  float u = fmaxf(f, 1.17549435e-38f);
  float t = -acc_logf(u);
  return -acc_logf(t);
}

// ---------------- packed f32x2 helpers ----------------
__device__ __forceinline__ void fma2(unsigned long long &acc, unsigned long long a, unsigned long long b){
  asm("fma.rn.f32x2 %0, %1, %2, %0;" : "+l"(acc) : "l"(a), "l"(b));
}
__device__ __forceinline__ unsigned long long pack2(float x, float y){
  unsigned long long r; asm("mov.b64 %0, {%1, %2};" : "=l"(r) : "f"(x), "f"(y)); return r;
}
__device__ __forceinline__ float2 unpack2(unsigned long long v){
  float2 r; asm("mov.b64 {%0, %1}, %2;" : "=f"(r.x), "=f"(r.y) : "l"(v)); return r;
}

// ---------------- init ----------------
__global__ void init_kernel(const float* __restrict__ encoded){
  int gid = blockIdx.x * blockDim.x + threadIdx.x;
  d_x[gid] = encoded[gid];
  d_h[gid] = 0.f;
  d_c[gid] = 0.f;
  if (gid < BB) d_active[gid] = 1;
  if (gid < SS) d_keys[gid] = tf2x32(0u, 42u, 0u, (unsigned)gid);
}

// ---------------- gates: [B,4H] = x@Wi^T + h@Wh^T + bias ----------------
// grid (16 rowblocks, 8 batchgroups) x 128 threads; block = 128 gate rows x 4 batches
__global__ void __launch_bounds__(128) gates_kernel(const float* __restrict__ Wi,
                                                    const float* __restrict__ Wh,
                                                    const float* __restrict__ bi,
                                                    const float* __restrict__ bh){
  __shared__ ulonglong2 sx2[EE];   // {pair(b0,b0+1), pair(b0+2,b0+3)} per k : 8 KB
  __shared__ ulonglong2 sh2[HH];   // 8 KB
  int b0 = blockIdx.y * 4;
  for (int i = threadIdx.x; i < EE; i += 128){
    ulonglong2 vx, vh;
    vx.x = pack2(d_x[(b0+0)*EE + i], d_x[(b0+1)*EE + i]);
    vx.y = pack2(d_x[(b0+2)*EE + i], d_x[(b0+3)*EE + i]);
    vh.x = pack2(d_h[(b0+0)*HH + i], d_h[(b0+1)*HH + i]);
    vh.y = pack2(d_h[(b0+2)*HH + i], d_h[(b0+3)*HH + i]);
    sx2[i] = vx; sh2[i] = vh;
  }
  __syncthreads();

  int j = blockIdx.x * 128 + threadIdx.x;   // gate row 0..2047
  const float4* wi = reinterpret_cast<const float4*>(Wi + (size_t)j * EE);
  const float4* wh = reinterpret_cast<const float4*>(Wh + (size_t)j * HH);
  unsigned long long ax0 = 0ull, ax1 = 0ull, ah0 = 0ull, ah1 = 0ull;
#pragma unroll 2
  for (int kq = 0; kq < EE/4; ++kq){
    float4 a = __ldg(wi + kq);
    float4 b = __ldg(wh + kq);
#pragma unroll
    for (int kk = 0; kk < 4; ++kk){
      ulonglong2 xv = sx2[kq*4 + kk];
      ulonglong2 hv = sh2[kq*4 + kk];
      float wa = (&a.x)[kk], wb = (&b.x)[kk];
      unsigned long long pa = pack2(wa, wa);
      unsigned long long pb = pack2(wb, wb);
      fma2(ax0, pa, xv.x); fma2(ax1, pa, xv.y);
      fma2(ah0, pb, hv.x); fma2(ah1, pb, hv.y);
    }
  }
  float bias = bi[j] + bh[j];
  float2 x0 = unpack2(ax0), x1 = unpack2(ax1);
  float2 h0 = unpack2(ah0), h1 = unpack2(ah1);
  d_gates[(b0+0)*GG + j] = x0.x + h0.x + bias;
  d_gates[(b0+1)*GG + j] = x0.y + h0.y + bias;
  d_gates[(b0+2)*GG + j] = x1.x + h1.x + bias;
  d_gates[(b0+3)*GG + j] = x1.y + h1.y + bias;
}

// ---------------- LSTM cell + half-major pair-transposed h write ----------------
__global__ void cell_kernel(){
  int b = blockIdx.x, k = threadIdx.x;
  float ig = d_gates[b*GG + k];
  float fg = d_gates[b*GG + 512 + k];
  float gg = d_gates[b*GG + 1024 + k];
  float og = d_gates[b*GG + 1536 + k];
  ig = 1.f / (1.f + expf(-ig));
  fg = 1.f / (1.f + expf(-fg));
  og = 1.f / (1.f + expf(-og));
  gg = tanhf(gg);
  float c = fg * d_c[b*HH + k] + ig * gg;
  d_c[b*HH + k] = c;
  float hval = og * tanhf(c);
  d_h[b*HH + k] = hval;
  // d_h2h[hf][k][pair] : hf = b>>4, pair = (b&15)>>1, word = b&1
  int hf = b >> 4, q = (b & 15) >> 1, wsel = b & 1;
  reinterpret_cast<unsigned*>(d_h2h)[((hf*HH + k)*8 + q)*2 + wsel] = __float_as_uint(hval);
}

// ---------------- vocab logits: [B,V] = h@Wo^T + bo ----------------
// grid (125 rowblocks, 2 batch-halves) x 128 threads.
// Thread: 2 vocab rows (r0, r0+128) x 16 batches (8 f32x2 accs per row).
__global__ void __launch_bounds__(128) logits_kernel(const float* __restrict__ Wo,
                                                     const float* __restrict__ bo){
  __shared__ unsigned long long h2[HH*8];             // 32 KB: [k][8 pairs] for this half
  int hf = blockIdx.y;
  {
    const ulonglong2* src = reinterpret_cast<const ulonglong2*>(d_h2h + hf*HH*8);
    ulonglong2* dst = reinterpret_cast<ulonglong2*>(h2);
    for (int i = threadIdx.x; i < HH*4; i += 128) dst[i] = src[i];
  }
  __syncthreads();

  int r0 = blockIdx.x * 256 + threadIdx.x;            // rows r0 and r0+128
  const float4* w0 = reinterpret_cast<const float4*>(Wo + (size_t)r0 * HH);
  const float4* w1 = reinterpret_cast<const float4*>(Wo + (size_t)(r0+128) * HH);

  unsigned long long acc[16];
#pragma unroll
  for (int p = 0; p < 16; ++p) acc[p] = 0ull;

  float4 a = __ldg(w0);
  float4 b = __ldg(w1);
  for (int kq = 0; kq < HH/4; ++kq){
    float4 na, nb;
    if (kq < HH/4 - 1){ na = __ldg(w0 + kq + 1); nb = __ldg(w1 + kq + 1); }
#pragma unroll
    for (int kk = 0; kk < 4; ++kk){
      const ulonglong2* hp = reinterpret_cast<const ulonglong2*>(h2 + (kq*4 + kk)*8);
      ulonglong2 v0 = hp[0], v1 = hp[1], v2 = hp[2], v3 = hp[3];
      float wa = (&a.x)[kk], wb = (&b.x)[kk];
      unsigned long long p0 = pack2(wa, wa);
      unsigned long long p1 = pack2(wb, wb);
      fma2(acc[0], p0, v0.x); fma2(acc[1], p0, v0.y);
      fma2(acc[2], p0, v1.x); fma2(acc[3], p0, v1.y);
      fma2(acc[4], p0, v2.x); fma2(acc[5], p0, v2.y);
      fma2(acc[6], p0, v3.x); fma2(acc[7], p0, v3.y);
      fma2(acc[8],  p1, v0.x); fma2(acc[9],  p1, v0.y);
      fma2(acc[10], p1, v1.x); fma2(acc[11], p1, v1.y);
      fma2(acc[12], p1, v2.x); fma2(acc[13], p1, v2.y);
      fma2(acc[14], p1, v3.x); fma2(acc[15], p1, v3.y);
    }
    a = na; b = nb;
  }

  float bv0 = __ldg(bo + r0), bv1 = __ldg(bo + r0 + 128);
#pragma unroll
  for (int p = 0; p < 8; ++p){
    float2 u0 = unpack2(acc[p]);
    float2 u1 = unpack2(acc[8+p]);
    int bb = hf*16 + 2*p;
    d_logits[(size_t)bb    *VV + r0      ] = u0.x + bv0;
    d_logits[(size_t)(bb+1)*VV + r0      ] = u0.y + bv0;
    d_logits[(size_t)bb    *VV + r0 + 128] = u1.x + bv1;
    d_logits[(size_t)(bb+1)*VV + r0 + 128] = u1.y + bv1;
  }
}

// ---------------- gumbel + partial argmax + partial sum(exp(logits)) ----------------
// grid (8 slices, 32 batches) x 256 threads; slice = 4000 vocab entries.
// |logits| <~ 3 by construction, so un-shifted exp is numerically safe.
__global__ void gumbel_kernel(int step){
  __shared__ float sv[256];
  __shared__ int   si[256];
  __shared__ float ss[256];
  int slice = blockIdx.x, b = blockIdx.y, tid = threadIdx.x;
  uint2 key = d_keys[step];
  float bm = -3.402823466e38f; int bidx = 0x7fffffff;
  float sum = 0.f;
  int v0 = slice * 4000;
  for (int v = v0 + tid; v < v0 + 4000; v += 256){
    float lg = d_logits[b*VV + v];
    sum += expf(lg);
    uint2 r = tf2x32(key.x, key.y, 0u, (unsigned)(b*VV + v));
    float sc = lg + gumbel_bits(r.x ^ r.y);
    if (sc > bm || (sc == bm && v < bidx)){ bm = sc; bidx = v; }
  }
  sv[tid] = bm; si[tid] = bidx; ss[tid] = sum; __syncthreads();
  for (int o = 128; o > 0; o >>= 1){
    if (tid < o){
      float ov = sv[tid+o]; int oi = si[tid+o];
      if (ov > sv[tid] || (ov == sv[tid] && oi < si[tid])){ sv[tid] = ov; si[tid] = oi; }
      ss[tid] += ss[tid+o];
    }
    __syncthreads();
  }
  if (tid == 0){
    d_pval[b*8 + slice] = sv[0];
    d_pidx[b*8 + slice] = si[0];
    d_psum[b*8 + slice] = ss[0];
  }
}

// ---------------- fused: rs from partials + logp store + token select + EOS + gather ----------------
__global__ void store_fin_kernel(float* __restrict__ out, int step,
                                 const float* __restrict__ emb){
  __shared__ float srs;
  __shared__ int stok;
  int b = blockIdx.x, tid = threadIdx.x;

  if (tid == 0){
    float S = 0.f;
#pragma unroll
    for (int s2 = 0; s2 < 8; ++s2) S += d_psum[b*8 + s2];
    srs = acc_logf(S);
    float bm = d_pval[b*8]; int bi_ = d_pidx[b*8];
#pragma unroll
    for (int s2 = 1; s2 < 8; ++s2){
      float v = d_pval[b*8 + s2]; int i2 = d_pidx[b*8 + s2];
      if (v > bm || (v == bm && i2 < bi_)){ bm = v; bi_ = i2; }
    }
    stok = bi_;
  }
  __syncthreads();
  float rs = srs;
  int act = d_active[b];

  const float4* row = reinterpret_cast<const float4*>(d_logits + b*VV);
  float4* orow = reinterpret_cast<float4*>(out + ((size_t)b * SS + step) * VV);
  for (int v = tid; v < VV/4; v += 1024){
    float4 x = row[v];
    float4 o4;
    o4.x = act ? x.x - rs : 0.0f;
    o4.y = act ? x.y - rs : 0.0f;
    o4.z = act ? x.z - rs : 0.0f;
    o4.w = act ? x.w - rs : 0.0f;
    orow[v] = o4;
  }

  if (tid == 0 && stok == VV - 2) d_active[b] = 0;   // EOS
  if (tid < EE) d_x[b*EE + tid] = emb[(size_t)stok*EE + tid];
}

// ---------------- launch ----------------
extern "C" void kernel_launch(void* const* d_in, const int* in_sizes, int n_in,
                              void* d_out, int out_size){
  const float* encoded = (const float*)d_in[0];
  const float* emb     = (const float*)d_in[1];
  const float* Wi      = (const float*)d_in[2];
  const float* Wh      = (const float*)d_in[3];
  const float* bi      = (const float*)d_in[4];
  const float* bh      = (const float*)d_in[5];
  const float* Wo      = (const float*)d_in[6];
  const float* bo      = (const float*)d_in[7];
  float* out = (float*)d_out;

  init_kernel<<<64, 256>>>(encoded);
  for (int s = 0; s < SS; ++s){
    gates_kernel<<<dim3(16, 8), 128>>>(Wi, Wh, bi, bh);
    cell_kernel<<<32, 512>>>();
    logits_kernel<<<dim3(125, 2), 128>>>(Wo, bo);
    gumbel_kernel<<<dim3(8, 32), 256>>>(s);
    store_fin_kernel<<<32, 1024>>>(out, s, emb);
  }
}

// round 6
// speedup vs baseline: 1.0919x; 1.0919x over previous
#include <cuda_runtime.h>
#include <cstdint>
#include <cstddef>

#define BB 32
#define SS 48
#define VV 32000
#define EE 512
#define HH 512
#define GG 2048

// ---------------- persistent device state ----------------
__device__ __align__(16) float d_x[BB*EE];
__device__ __align__(16) float d_h[BB*HH];
__device__ __align__(16) float d_c[BB*HH];
__device__ __align__(16) float d_gates[BB*GG];
__device__ __align__(16) float d_logits[BB*VV];
__device__ __align__(16) unsigned long long d_h2[HH*16];   // pair-major transposed h
__device__ float d_pval[BB*8];
__device__ int   d_pidx[BB*8];
__device__ float d_psum[BB*8];
__device__ int   d_active[BB];
__device__ uint2 d_keys[SS];

// ---------------- threefry2x32 (exact JAX algorithm, 20 rounds) ----------------
__device__ __forceinline__ uint2 tf2x32(unsigned k0, unsigned k1, unsigned x0, unsigned x1){
  unsigned k2 = 0x1BD11BDAu ^ k0 ^ k1;
  x0 += k0; x1 += k1;
#define TFRND(R) { x0 += x1; x1 = (x1 << (R)) | (x1 >> (32-(R))); x1 ^= x0; }
  TFRND(13) TFRND(15) TFRND(26) TFRND(6)
  x0 += k1; x1 += k2 + 1u;
  TFRND(17) TFRND(29) TFRND(16) TFRND(24)
  x0 += k2; x1 += k0 + 2u;
  TFRND(13) TFRND(15) TFRND(26) TFRND(6)
  x0 += k0; x1 += k1 + 3u;
  TFRND(17) TFRND(29) TFRND(16) TFRND(24)
  x0 += k1; x1 += k2 + 4u;
  TFRND(13) TFRND(15) TFRND(26) TFRND(6)
  x0 += k2; x1 += k0 + 5u;
#undef TFRND
  return make_uint2(x0, x1);
}

// ---------------- accurate logf (cephes-style, ~1 ulp; immune to fast-math) ----------------
__device__ __forceinline__ float acc_logf(float x){
  unsigned ix = __float_as_uint(x);
  unsigned off = ix + (0x3f800000u - 0x3f3504f3u);
  int k = ((int)(off >> 23)) - 127;
  unsigned mx = (off & 0x007fffffu) + 0x3f3504f3u;
  float f = __uint_as_float(mx) - 1.0f;
  float z = f * f;
  float p =              7.0376836292e-2f;
  p = fmaf(p, f, -1.1514610310e-1f);
  p = fmaf(p, f,  1.1676998740e-1f);
  p = fmaf(p, f, -1.2420140846e-1f);
  p = fmaf(p, f,  1.4249322787e-1f);
  p = fmaf(p, f, -1.6668057665e-1f);
  p = fmaf(p, f,  2.0000714765e-1f);
  p = fmaf(p, f, -2.4999993993e-1f);
  p = fmaf(p, f,  3.3333331174e-1f);
  float y = f * z * p;
  y = fmaf(-0.5f, z, y);
  float r = fmaf((float)k, -2.12194440e-4f, y);
  r = f + r;
  r = fmaf((float)k, 0.693359375f, r);
  return r;
}

__device__ __forceinline__ float gumbel_bits(unsigned bits){
  float f = __uint_as_float((bits >> 9) | 0x3f800000u) - 1.0f;
  float u = fmaxf(f, 1.17549435e-38f);
  float t = -acc_logf(u);
  return -acc_logf(t);
}

// ---------------- packed f32x2 helpers ----------------
__device__ __forceinline__ void fma2(unsigned long long &acc, unsigned long long a, unsigned long long b){
  asm("fma.rn.f32x2 %0, %1, %2, %0;" : "+l"(acc) : "l"(a), "l"(b));
}
__device__ __forceinline__ unsigned long long pack2(float x, float y){
  unsigned long long r; asm("mov.b64 %0, {%1, %2};" : "=l"(r) : "f"(x), "f"(y)); return r;
}
__device__ __forceinline__ float2 unpack2(unsigned long long v){
  float2 r; asm("mov.b64 {%0, %1}, %2;" : "=f"(r.x), "=f"(r.y) : "l"(v)); return r;
}

// ---------------- init ----------------
__global__ void init_kernel(const float* __restrict__ encoded){
  int gid = blockIdx.x * blockDim.x + threadIdx.x;
  d_x[gid] = encoded[gid];
  d_h[gid] = 0.f;
  d_c[gid] = 0.f;
  if (gid < BB) d_active[gid] = 1;
  if (gid < SS) d_keys[gid] = tf2x32(0u, 42u, 0u, (unsigned)gid);
}

// ---------------- gates: [B,4H] = x@Wi^T + h@Wh^T + bias ----------------
// grid (16 rowblocks, 8 batchgroups) x 128 threads; depth-4 prefetch ring on both weights
__global__ void __launch_bounds__(128) gates_kernel(const float* __restrict__ Wi,
                                                    const float* __restrict__ Wh,
                                                    const float* __restrict__ bi,
                                                    const float* __restrict__ bh){
  __shared__ ulonglong2 sx2[EE];
  __shared__ ulonglong2 sh2[HH];
  int b0 = blockIdx.y * 4;
  for (int i = threadIdx.x; i < EE; i += 128){
    ulonglong2 vx, vh;
    vx.x = pack2(d_x[(b0+0)*EE + i], d_x[(b0+1)*EE + i]);
    vx.y = pack2(d_x[(b0+2)*EE + i], d_x[(b0+3)*EE + i]);
    vh.x = pack2(d_h[(b0+0)*HH + i], d_h[(b0+1)*HH + i]);
    vh.y = pack2(d_h[(b0+2)*HH + i], d_h[(b0+3)*HH + i]);
    sx2[i] = vx; sh2[i] = vh;
  }
  __syncthreads();

  int j = blockIdx.x * 128 + threadIdx.x;   // gate row 0..2047
  const float4* wi = reinterpret_cast<const float4*>(Wi + (size_t)j * EE);
  const float4* wh = reinterpret_cast<const float4*>(Wh + (size_t)j * HH);

  float4 bi0 = __ldg(wi+0), bi1 = __ldg(wi+1), bi2 = __ldg(wi+2), bi3 = __ldg(wi+3);
  float4 bh0 = __ldg(wh+0), bh1 = __ldg(wh+1), bh2 = __ldg(wh+2), bh3 = __ldg(wh+3);

  unsigned long long ax0 = 0ull, ax1 = 0ull, ah0 = 0ull, ah1 = 0ull;

#define GPROC(WA, WB, KQI) { \
  _Pragma("unroll") for (int kk = 0; kk < 4; ++kk){ \
    ulonglong2 xv = sx2[(KQI)*4 + kk]; \
    ulonglong2 hv = sh2[(KQI)*4 + kk]; \
    float wa = (&WA.x)[kk], wb = (&WB.x)[kk]; \
    unsigned long long pa = pack2(wa, wa); \
    unsigned long long pb = pack2(wb, wb); \
    fma2(ax0, pa, xv.x); fma2(ax1, pa, xv.y); \
    fma2(ah0, pb, hv.x); fma2(ah1, pb, hv.y); } }

#pragma unroll 1
  for (int kq = 0; kq < EE/4; kq += 4){
    float4 ci0 = bi0, ci1 = bi1, ci2 = bi2, ci3 = bi3;
    float4 ch0 = bh0, ch1 = bh1, ch2 = bh2, ch3 = bh3;
    if (kq + 4 < EE/4){
      bi0 = __ldg(wi + kq + 4); bi1 = __ldg(wi + kq + 5);
      bi2 = __ldg(wi + kq + 6); bi3 = __ldg(wi + kq + 7);
      bh0 = __ldg(wh + kq + 4); bh1 = __ldg(wh + kq + 5);
      bh2 = __ldg(wh + kq + 6); bh3 = __ldg(wh + kq + 7);
    }
    GPROC(ci0, ch0, kq+0)
    GPROC(ci1, ch1, kq+1)
    GPROC(ci2, ch2, kq+2)
    GPROC(ci3, ch3, kq+3)
  }
#undef GPROC

  float bias = bi[j] + bh[j];
  float2 x0 = unpack2(ax0), x1 = unpack2(ax1);
  float2 h0 = unpack2(ah0), h1 = unpack2(ah1);
  d_gates[(b0+0)*GG + j] = x0.x + h0.x + bias;
  d_gates[(b0+1)*GG + j] = x0.y + h0.y + bias;
  d_gates[(b0+2)*GG + j] = x1.x + h1.x + bias;
  d_gates[(b0+3)*GG + j] = x1.y + h1.y + bias;
}

// ---------------- LSTM cell + pair-major transposed h write ----------------
__global__ void cell_kernel(){
  int b = blockIdx.x, k = threadIdx.x;
  float ig = d_gates[b*GG + k];
  float fg = d_gates[b*GG + 512 + k];
  float gg = d_gates[b*GG + 1024 + k];
  float og = d_gates[b*GG + 1536 + k];
  ig = 1.f / (1.f + expf(-ig));
  fg = 1.f / (1.f + expf(-fg));
  og = 1.f / (1.f + expf(-og));
  gg = tanhf(gg);
  float c = fg * d_c[b*HH + k] + ig * gg;
  d_c[b*HH + k] = c;
  float hval = og * tanhf(c);
  d_h[b*HH + k] = hval;
  // h2[k*16 + pair] = pack(h[2p][k], h[2p+1][k])
  reinterpret_cast<unsigned*>(d_h2)[(k*16 + (b>>1))*2 + (b&1)] = __float_as_uint(hval);
}

// ---------------- vocab logits: [B,V] = h@Wo^T + bo ----------------
// 125 blocks x 256 threads; thread = 1 vocab row x 32 batches (16 f32x2 accs).
// Weight stream: depth-4 float4 prefetch ring (4 LDG.128 in flight, ~700cyc lookahead).
__global__ void __launch_bounds__(256) logits_kernel(const float* __restrict__ Wo,
                                                     const float* __restrict__ bo){
  extern __shared__ unsigned long long h2[];          // HH*16 u64 = 64KB
  {
    const ulonglong2* src = reinterpret_cast<const ulonglong2*>(d_h2);
    ulonglong2* dst = reinterpret_cast<ulonglong2*>(h2);
    for (int i = threadIdx.x; i < HH*8; i += 256) dst[i] = src[i];
  }
  __syncthreads();

  int r = blockIdx.x * 256 + threadIdx.x;             // one vocab row per thread
  const float4* w = reinterpret_cast<const float4*>(Wo + (size_t)r * HH);

  unsigned long long acc[16];
#pragma unroll
  for (int p = 0; p < 16; ++p) acc[p] = 0ull;

  float4 b0 = __ldg(w+0), b1 = __ldg(w+1), b2 = __ldg(w+2), b3 = __ldg(w+3);

#define LPROC(WV, KQI) { \
  _Pragma("unroll") for (int kk = 0; kk < 4; ++kk){ \
    const ulonglong2* hp = reinterpret_cast<const ulonglong2*>(h2) + ((KQI)*4 + kk)*8; \
    ulonglong2 v0 = hp[0], v1 = hp[1], v2 = hp[2], v3 = hp[3]; \
    ulonglong2 v4 = hp[4], v5 = hp[5], v6 = hp[6], v7 = hp[7]; \
    float ws = (&WV.x)[kk]; \
    unsigned long long pw = pack2(ws, ws); \
    fma2(acc[0],  pw, v0.x); fma2(acc[1],  pw, v0.y); \
    fma2(acc[2],  pw, v1.x); fma2(acc[3],  pw, v1.y); \
    fma2(acc[4],  pw, v2.x); fma2(acc[5],  pw, v2.y); \
    fma2(acc[6],  pw, v3.x); fma2(acc[7],  pw, v3.y); \
    fma2(acc[8],  pw, v4.x); fma2(acc[9],  pw, v4.y); \
    fma2(acc[10], pw, v5.x); fma2(acc[11], pw, v5.y); \
    fma2(acc[12], pw, v6.x); fma2(acc[13], pw, v6.y); \
    fma2(acc[14], pw, v7.x); fma2(acc[15], pw, v7.y); } }

#pragma unroll 1
  for (int kq = 0; kq < HH/4; kq += 4){
    float4 c0 = b0, c1 = b1, c2 = b2, c3 = b3;
    if (kq + 4 < HH/4){
      b0 = __ldg(w + kq + 4); b1 = __ldg(w + kq + 5);
      b2 = __ldg(w + kq + 6); b3 = __ldg(w + kq + 7);
    }
    LPROC(c0, kq+0)
    LPROC(c1, kq+1)
    LPROC(c2, kq+2)
    LPROC(c3, kq+3)
  }
#undef LPROC

  float bv = __ldg(bo + r);
#pragma unroll
  for (int p = 0; p < 16; ++p){
    float2 v = unpack2(acc[p]);
    d_logits[(size_t)(2*p)  *VV + r] = v.x + bv;
    d_logits[(size_t)(2*p+1)*VV + r] = v.y + bv;
  }
}

// ---------------- gumbel + partial argmax + partial sum(exp(logits)) ----------------
__global__ void gumbel_kernel(int step){
  __shared__ float sv[256];
  __shared__ int   si[256];
  __shared__ float ss[256];
  int slice = blockIdx.x, b = blockIdx.y, tid = threadIdx.x;
  uint2 key = d_keys[step];
  float bm = -3.402823466e38f; int bidx = 0x7fffffff;
  float sum = 0.f;
  int v0 = slice * 4000;
  for (int v = v0 + tid; v < v0 + 4000; v += 256){
    float lg = d_logits[b*VV + v];
    sum += expf(lg);
    uint2 r = tf2x32(key.x, key.y, 0u, (unsigned)(b*VV + v));
    float sc = lg + gumbel_bits(r.x ^ r.y);
    if (sc > bm || (sc == bm && v < bidx)){ bm = sc; bidx = v; }
  }
  sv[tid] = bm; si[tid] = bidx; ss[tid] = sum; __syncthreads();
  for (int o = 128; o > 0; o >>= 1){
    if (tid < o){
      float ov = sv[tid+o]; int oi = si[tid+o];
      if (ov > sv[tid] || (ov == sv[tid] && oi < si[tid])){ sv[tid] = ov; si[tid] = oi; }
      ss[tid] += ss[tid+o];
    }
    __syncthreads();
  }
  if (tid == 0){
    d_pval[b*8 + slice] = sv[0];
    d_pidx[b*8 + slice] = si[0];
    d_psum[b*8 + slice] = ss[0];
  }
}

// ---------------- fused: rs + logp store + token select + EOS + embed gather ----------------
__global__ void store_fin_kernel(float* __restrict__ out, int step,
                                 const float* __restrict__ emb){
  __shared__ float srs;
  __shared__ int stok;
  int b = blockIdx.x, tid = threadIdx.x;

  if (tid == 0){
    float S = 0.f;
#pragma unroll
    for (int s2 = 0; s2 < 8; ++s2) S += d_psum[b*8 + s2];
    srs = acc_logf(S);
    float bm = d_pval[b*8]; int bi_ = d_pidx[b*8];
#pragma unroll
    for (int s2 = 1; s2 < 8; ++s2){
      float v = d_pval[b*8 + s2]; int i2 = d_pidx[b*8 + s2];
      if (v > bm || (v == bm && i2 < bi_)){ bm = v; bi_ = i2; }
    }
    stok = bi_;
  }
  __syncthreads();
  float rs = srs;
  int act = d_active[b];

  const float4* row = reinterpret_cast<const float4*>(d_logits + b*VV);
  float4* orow = reinterpret_cast<float4*>(out + ((size_t)b * SS + step) * VV);
  for (int v = tid; v < VV/4; v += 1024){
    float4 x = row[v];
    float4 o4;
    o4.x = act ? x.x - rs : 0.0f;
    o4.y = act ? x.y - rs : 0.0f;
    o4.z = act ? x.z - rs : 0.0f;
    o4.w = act ? x.w - rs : 0.0f;
    orow[v] = o4;
  }

  if (tid == 0 && stok == VV - 2) d_active[b] = 0;   // EOS
  if (tid < EE) d_x[b*EE + tid] = emb[(size_t)stok*EE + tid];
}

// ---------------- launch ----------------
extern "C" void kernel_launch(void* const* d_in, const int* in_sizes, int n_in,
                              void* d_out, int out_size){
  const float* encoded = (const float*)d_in[0];
  const float* emb     = (const float*)d_in[1];
  const float* Wi      = (const float*)d_in[2];
  const float* Wh      = (const float*)d_in[3];
  const float* bi      = (const float*)d_in[4];
  const float* bh      = (const float*)d_in[5];
  const float* Wo      = (const float*)d_in[6];
  const float* bo      = (const float*)d_in[7];
  float* out = (float*)d_out;

  cudaFuncSetAttribute(logits_kernel, cudaFuncAttributeMaxDynamicSharedMemorySize, 65536);

  init_kernel<<<64, 256>>>(encoded);
  for (int s = 0; s < SS; ++s){
    gates_kernel<<<dim3(16, 8), 128>>>(Wi, Wh, bi, bh);
    cell_kernel<<<32, 512>>>();
    logits_kernel<<<125, 256, 65536>>>(Wo, bo);
    gumbel_kernel<<<dim3(8, 32), 256>>>(s);
    store_fin_kernel<<<32, 1024>>>(out, s, emb);
  }
}

// round 7
// speedup vs baseline: 1.8595x; 1.7030x over previous
#include <cuda_runtime.h>
#include <cstdint>
#include <cstddef>

#define BB 32
#define SS 48
#define VV 32000
#define EE 512
#define HH 512
#define GG 2048
#define NSLICE 16

// ---------------- persistent device state ----------------
__device__ __align__(16) float d_x[BB*EE];
__device__ __align__(16) float d_h[BB*HH];
__device__ __align__(16) float d_c[BB*HH];
__device__ __align__(16) float d_gates[BB*GG];
__device__ __align__(16) float d_part0[BB*VV];
__device__ __align__(16) float d_part1[BB*VV];
__device__ __align__(16) unsigned long long d_h2[HH*16];   // pair-major transposed h
__device__ float d_pval[BB*NSLICE];
__device__ int   d_pidx[BB*NSLICE];
__device__ float d_psum[BB*NSLICE];
__device__ int   d_active[BB];
__device__ uint2 d_keys[SS];

// ---------------- threefry2x32 (exact JAX algorithm, 20 rounds) ----------------
__device__ __forceinline__ uint2 tf2x32(unsigned k0, unsigned k1, unsigned x0, unsigned x1){
  unsigned k2 = 0x1BD11BDAu ^ k0 ^ k1;
  x0 += k0; x1 += k1;
#define TFRND(R) { x0 += x1; x1 = (x1 << (R)) | (x1 >> (32-(R))); x1 ^= x0; }
  TFRND(13) TFRND(15) TFRND(26) TFRND(6)
  x0 += k1; x1 += k2 + 1u;
  TFRND(17) TFRND(29) TFRND(16) TFRND(24)
  x0 += k2; x1 += k0 + 2u;
  TFRND(13) TFRND(15) TFRND(26) TFRND(6)
  x0 += k0; x1 += k1 + 3u;
  TFRND(17) TFRND(29) TFRND(16) TFRND(24)
  x0 += k1; x1 += k2 + 4u;
  TFRND(13) TFRND(15) TFRND(26) TFRND(6)
  x0 += k2; x1 += k0 + 5u;
#undef TFRND
  return make_uint2(x0, x1);
}

// ---------------- accurate logf (~1 ulp; immune to fast-math) ----------------
__device__ __forceinline__ float acc_logf(float x){
  unsigned ix = __float_as_uint(x);
  unsigned off = ix + (0x3f800000u - 0x3f3504f3u);
  int k = ((int)(off >> 23)) - 127;
  unsigned mx = (off & 0x007fffffu) + 0x3f3504f3u;
  float f = __uint_as_float(mx) - 1.0f;
  float z = f * f;
  float p =              7.0376836292e-2f;
  p = fmaf(p, f, -1.1514610310e-1f);
  p = fmaf(p, f,  1.1676998740e-1f);
  p = fmaf(p, f, -1.2420140846e-1f);
  p = fmaf(p, f,  1.4249322787e-1f);
  p = fmaf(p, f, -1.6668057665e-1f);
  p = fmaf(p, f,  2.0000714765e-1f);
  p = fmaf(p, f, -2.4999993993e-1f);
  p = fmaf(p, f,  3.3333331174e-1f);
  float y = f * z * p;
  y = fmaf(-0.5f, z, y);
  float r = fmaf((float)k, -2.12194440e-4f, y);
  r = f + r;
  r = fmaf((float)k, 0.693359375f, r);
  return r;
}

__device__ __forceinline__ float gumbel_bits(unsigned bits){
  float f = __uint_as_float((bits >> 9) | 0x3f800000u) - 1.0f;
  float u = fmaxf(f, 1.17549435e-38f);
  float t = -acc_logf(u);
  return -acc_logf(t);
}

// ---------------- packed f32x2 helpers ----------------
__device__ __forceinline__ void fma2(unsigned long long &acc, unsigned long long a, unsigned long long b){
  asm("fma.rn.f32x2 %0, %1, %2, %0;" : "+l"(acc) : "l"(a), "l"(b));
}
__device__ __forceinline__ unsigned long long pack2(float x, float y){
  unsigned long long r; asm("mov.b64 %0, {%1, %2};" : "=l"(r) : "f"(x), "f"(y)); return r;
}
__device__ __forceinline__ float2 unpack2(unsigned long long v){
  float2 r; asm("mov.b64 {%0, %1}, %2;" : "=f"(r.x), "=f"(r.y) : "l"(v)); return r;
}

// combined logit (IDENTICAL expression in gumbel & store paths)
__device__ __forceinline__ float comb_logit(float p0, float p1, float bv){
  return (p0 + p1) + bv;
}

// ---------------- init ----------------
__global__ void init_kernel(const float* __restrict__ encoded){
  int gid = blockIdx.x * blockDim.x + threadIdx.x;
  d_x[gid] = encoded[gid];
  d_h[gid] = 0.f;
  d_c[gid] = 0.f;
  if (gid < BB) d_active[gid] = 1;
  if (gid < SS) d_keys[gid] = tf2x32(0u, 42u, 0u, (unsigned)gid);
}

// ---------------- gates: [B,4H] = x@Wi^T + h@Wh^T + bias ----------------
__global__ void __launch_bounds__(128) gates_kernel(const float* __restrict__ Wi,
                                                    const float* __restrict__ Wh,
                                                    const float* __restrict__ bi,
                                                    const float* __restrict__ bh){
  __shared__ ulonglong2 sx2[EE];
  __shared__ ulonglong2 sh2[HH];
  int b0 = blockIdx.y * 4;
  for (int i = threadIdx.x; i < EE; i += 128){
    ulonglong2 vx, vh;
    vx.x = pack2(d_x[(b0+0)*EE + i], d_x[(b0+1)*EE + i]);
    vx.y = pack2(d_x[(b0+2)*EE + i], d_x[(b0+3)*EE + i]);
    vh.x = pack2(d_h[(b0+0)*HH + i], d_h[(b0+1)*HH + i]);
    vh.y = pack2(d_h[(b0+2)*HH + i], d_h[(b0+3)*HH + i]);
    sx2[i] = vx; sh2[i] = vh;
  }
  __syncthreads();

  int j = blockIdx.x * 128 + threadIdx.x;
  const float4* wi = reinterpret_cast<const float4*>(Wi + (size_t)j * EE);
  const float4* wh = reinterpret_cast<const float4*>(Wh + (size_t)j * HH);
  unsigned long long ax0 = 0ull, ax1 = 0ull, ah0 = 0ull, ah1 = 0ull;
#pragma unroll 2
  for (int kq = 0; kq < EE/4; ++kq){
    float4 a = __ldg(wi + kq);
    float4 b = __ldg(wh + kq);
#pragma unroll
    for (int kk = 0; kk < 4; ++kk){
      ulonglong2 xv = sx2[kq*4 + kk];
      ulonglong2 hv = sh2[kq*4 + kk];
      float wa = (&a.x)[kk], wb = (&b.x)[kk];
      unsigned long long pa = pack2(wa, wa);
      unsigned long long pb = pack2(wb, wb);
      fma2(ax0, pa, xv.x); fma2(ax1, pa, xv.y);
      fma2(ah0, pb, hv.x); fma2(ah1, pb, hv.y);
    }
  }
  float bias = bi[j] + bh[j];
  float2 x0 = unpack2(ax0), x1 = unpack2(ax1);
  float2 h0 = unpack2(ah0), h1 = unpack2(ah1);
  d_gates[(b0+0)*GG + j] = x0.x + h0.x + bias;
  d_gates[(b0+1)*GG + j] = x0.y + h0.y + bias;
  d_gates[(b0+2)*GG + j] = x1.x + h1.x + bias;
  d_gates[(b0+3)*GG + j] = x1.y + h1.y + bias;
}

// ---------------- LSTM cell + pair-major transposed h write ----------------
__global__ void cell_kernel(){
  int b = blockIdx.x, k = threadIdx.x;
  float ig = d_gates[b*GG + k];
  float fg = d_gates[b*GG + 512 + k];
  float gg = d_gates[b*GG + 1024 + k];
  float og = d_gates[b*GG + 1536 + k];
  ig = 1.f / (1.f + expf(-ig));
  fg = 1.f / (1.f + expf(-fg));
  og = 1.f / (1.f + expf(-og));
  gg = tanhf(gg);
  float c = fg * d_c[b*HH + k] + ig * gg;
  d_c[b*HH + k] = c;
  float hval = og * tanhf(c);
  d_h[b*HH + k] = hval;
  reinterpret_cast<unsigned*>(d_h2)[(k*16 + (b>>1))*2 + (b&1)] = __float_as_uint(hval);
}

// ---------------- vocab logits, split-K: partial[B,V] = h[,kh] @ Wo[,kh]^T ----------------
// grid (63 rowblocks, 2 khalves) x 256 threads.
// Thread: 2 vocab rows (r0 = base+tid, r1 = base+256+tid) x 32 batches, K-half of 256.
__global__ void __launch_bounds__(256) logits_kernel(const float* __restrict__ Wo){
  __shared__ unsigned long long h2[256*16];           // 32 KB: this k-half, pair-major
  int kh = blockIdx.y;
  {
    const ulonglong2* src = reinterpret_cast<const ulonglong2*>(d_h2 + kh*256*16);
    ulonglong2* dst = reinterpret_cast<ulonglong2*>(h2);
    for (int i = threadIdx.x; i < 256*8; i += 256) dst[i] = src[i];
  }
  __syncthreads();

  int base = blockIdx.x * 512;
  int r0 = base + threadIdx.x;
  int r1 = base + 256 + threadIdx.x;
  bool v1 = (r1 < VV);                                 // last block: r1 range is OOB
  const float4* w0 = reinterpret_cast<const float4*>(Wo + (size_t)r0 * HH + kh*256);
  const float4* w1 = reinterpret_cast<const float4*>(Wo + (size_t)(v1 ? r1 : r0) * HH + kh*256);

  unsigned long long acc0[16], acc1[16];
#pragma unroll
  for (int p = 0; p < 16; ++p){ acc0[p] = 0ull; acc1[p] = 0ull; }

  float4 a = __ldg(w0);
  float4 b = __ldg(w1);
#pragma unroll 1
  for (int kq = 0; kq < 64; ++kq){
    float4 ca = a, cb = b;
    if (kq < 63){ a = __ldg(w0 + kq + 1); b = __ldg(w1 + kq + 1); }
#pragma unroll
    for (int kk = 0; kk < 4; ++kk){
      const ulonglong2* hp = reinterpret_cast<const ulonglong2*>(h2) + (kq*4 + kk)*8;
      ulonglong2 v0_ = hp[0], v1_ = hp[1], v2_ = hp[2], v3_ = hp[3];
      ulonglong2 v4_ = hp[4], v5_ = hp[5], v6_ = hp[6], v7_ = hp[7];
      float wa = (&ca.x)[kk], wb = (&cb.x)[kk];
      unsigned long long pa = pack2(wa, wa);
      unsigned long long pb = pack2(wb, wb);
      fma2(acc0[0],  pa, v0_.x); fma2(acc0[1],  pa, v0_.y);
      fma2(acc0[2],  pa, v1_.x); fma2(acc0[3],  pa, v1_.y);
      fma2(acc0[4],  pa, v2_.x); fma2(acc0[5],  pa, v2_.y);
      fma2(acc0[6],  pa, v3_.x); fma2(acc0[7],  pa, v3_.y);
      fma2(acc0[8],  pa, v4_.x); fma2(acc0[9],  pa, v4_.y);
      fma2(acc0[10], pa, v5_.x); fma2(acc0[11], pa, v5_.y);
      fma2(acc0[12], pa, v6_.x); fma2(acc0[13], pa, v6_.y);
      fma2(acc0[14], pa, v7_.x); fma2(acc0[15], pa, v7_.y);
      fma2(acc1[0],  pb, v0_.x); fma2(acc1[1],  pb, v0_.y);
      fma2(acc1[2],  pb, v1_.x); fma2(acc1[3],  pb, v1_.y);
      fma2(acc1[4],  pb, v2_.x); fma2(acc1[5],  pb, v2_.y);
      fma2(acc1[6],  pb, v3_.x); fma2(acc1[7],  pb, v3_.y);
      fma2(acc1[8],  pb, v4_.x); fma2(acc1[9],  pb, v4_.y);
      fma2(acc1[10], pb, v5_.x); fma2(acc1[11], pb, v5_.y);
      fma2(acc1[12], pb, v6_.x); fma2(acc1[13], pb, v6_.y);
      fma2(acc1[14], pb, v7_.x); fma2(acc1[15], pb, v7_.y);
    }
  }

  float* dst = kh ? d_part1 : d_part0;
#pragma unroll
  for (int p = 0; p < 16; ++p){
    float2 u0 = unpack2(acc0[p]);
    dst[(size_t)(2*p)  *VV + r0] = u0.x;
    dst[(size_t)(2*p+1)*VV + r0] = u0.y;
  }
  if (v1){
#pragma unroll
    for (int p = 0; p < 16; ++p){
      float2 u1 = unpack2(acc1[p]);
      dst[(size_t)(2*p)  *VV + r1] = u1.x;
      dst[(size_t)(2*p+1)*VV + r1] = u1.y;
    }
  }
}

// ---------------- gumbel + partial argmax + partial sum(exp(logit)) ----------------
// grid (16 slices, 32 batches) x 256 threads; slice = 2000 vocab entries.
__global__ void gumbel_kernel(int step, const float* __restrict__ bo){
  __shared__ float sv[256];
  __shared__ int   si[256];
  __shared__ float ss[256];
  int slice = blockIdx.x, b = blockIdx.y, tid = threadIdx.x;
  uint2 key = d_keys[step];
  float bm = -3.402823466e38f; int bidx = 0x7fffffff;
  float sum = 0.f;
  int v0 = slice * 2000;
  for (int v = v0 + tid; v < v0 + 2000; v += 256){
    float lg = comb_logit(d_part0[b*VV + v], d_part1[b*VV + v], __ldg(bo + v));
    sum += expf(lg);
    uint2 r = tf2x32(key.x, key.y, 0u, (unsigned)(b*VV + v));
    float sc = lg + gumbel_bits(r.x ^ r.y);
    if (sc > bm || (sc == bm && v < bidx)){ bm = sc; bidx = v; }
  }
  sv[tid] = bm; si[tid] = bidx; ss[tid] = sum; __syncthreads();
  for (int o = 128; o > 0; o >>= 1){
    if (tid < o){
      float ov = sv[tid+o]; int oi = si[tid+o];
      if (ov > sv[tid] || (ov == sv[tid] && oi < si[tid])){ sv[tid] = ov; si[tid] = oi; }
      ss[tid] += ss[tid+o];
    }
    __syncthreads();
  }
  if (tid == 0){
    d_pval[b*NSLICE + slice] = sv[0];
    d_pidx[b*NSLICE + slice] = si[0];
    d_psum[b*NSLICE + slice] = ss[0];
  }
}

// ---------------- fused: rs + logp store + token select + EOS + embed gather ----------------
__global__ void store_fin_kernel(float* __restrict__ out, int step,
                                 const float* __restrict__ emb,
                                 const float* __restrict__ bo){
  __shared__ float srs;
  __shared__ int stok;
  int b = blockIdx.x, tid = threadIdx.x;

  if (tid == 0){
    float S = 0.f;
#pragma unroll
    for (int s2 = 0; s2 < NSLICE; ++s2) S += d_psum[b*NSLICE + s2];
    srs = acc_logf(S);
    float bm = d_pval[b*NSLICE]; int bi_ = d_pidx[b*NSLICE];
#pragma unroll
    for (int s2 = 1; s2 < NSLICE; ++s2){
      float v = d_pval[b*NSLICE + s2]; int i2 = d_pidx[b*NSLICE + s2];
      if (v > bm || (v == bm && i2 < bi_)){ bm = v; bi_ = i2; }
    }
    stok = bi_;
  }
  __syncthreads();
  float rs = srs;
  int act = d_active[b];

  const float4* p0 = reinterpret_cast<const float4*>(d_part0 + b*VV);
  const float4* p1 = reinterpret_cast<const float4*>(d_part1 + b*VV);
  const float4* bq = reinterpret_cast<const float4*>(bo);
  float4* orow = reinterpret_cast<float4*>(out + ((size_t)b * SS + step) * VV);
  for (int v = tid; v < VV/4; v += 1024){
    float4 a = p0[v], c = p1[v], d = __ldg(bq + v);
    float4 o4;
    o4.x = act ? comb_logit(a.x, c.x, d.x) - rs : 0.0f;
    o4.y = act ? comb_logit(a.y, c.y, d.y) - rs : 0.0f;
    o4.z = act ? comb_logit(a.z, c.z, d.z) - rs : 0.0f;
    o4.w = act ? comb_logit(a.w, c.w, d.w) - rs : 0.0f;
    orow[v] = o4;
  }

  if (tid == 0 && stok == VV - 2) d_active[b] = 0;   // EOS
  if (tid < EE) d_x[b*EE + tid] = emb[(size_t)stok*EE + tid];
}

// ---------------- launch ----------------
extern "C" void kernel_launch(void* const* d_in, const int* in_sizes, int n_in,
                              void* d_out, int out_size){
  const float* encoded = (const float*)d_in[0];
  const float* emb     = (const float*)d_in[1];
  const float* Wi      = (const float*)d_in[2];
  const float* Wh      = (const float*)d_in[3];
  const float* bi      = (const float*)d_in[4];
  const float* bh      = (const float*)d_in[5];
  const float* Wo      = (const float*)d_in[6];
  const float* bo      = (const float*)d_in[7];
  float* out = (float*)d_out;

  init_kernel<<<64, 256>>>(encoded);
  for (int s = 0; s < SS; ++s){
    gates_kernel<<<dim3(16, 8), 128>>>(Wi, Wh, bi, bh);
    cell_kernel<<<32, 512>>>();
    logits_kernel<<<dim3(63, 2), 256>>>(Wo);
    gumbel_kernel<<<dim3(NSLICE, 32), 256>>>(s, bo);
    store_fin_kernel<<<32, 1024>>>(out, s, emb, bo);
  }
}

// round 8
// speedup vs baseline: 1.9270x; 1.0363x over previous
#include <cuda_runtime.h>
#include <cstdint>
#include <cstddef>

#define BB 32
#define SS 48
#define VV 32000
#define EE 512
#define HH 512
#define GG 2048
#define NSLICE 16

// ---------------- persistent device state ----------------
__device__ __align__(16) float d_x[BB*EE];
__device__ __align__(16) float d_h[BB*HH];
__device__ __align__(16) float d_c[BB*HH];
__device__ __align__(16) float d_gates[BB*GG];
__device__ __align__(16) float d_part[4][BB*VV];           // split-K partials (16 MB)
__device__ __align__(16) float d_logits[BB*VV];            // combined logits (gumbel output)
__device__ __align__(16) unsigned long long d_h2[HH*16];   // pair-major transposed h
__device__ float d_pval[BB*NSLICE];
__device__ int   d_pidx[BB*NSLICE];
__device__ float d_psum[BB*NSLICE];
__device__ int   d_act[2][BB];                             // ping-pong active flags
__device__ uint2 d_keys[SS];

// ---------------- threefry2x32 (exact JAX algorithm, 20 rounds) ----------------
__device__ __forceinline__ uint2 tf2x32(unsigned k0, unsigned k1, unsigned x0, unsigned x1){
  unsigned k2 = 0x1BD11BDAu ^ k0 ^ k1;
  x0 += k0; x1 += k1;
#define TFRND(R) { x0 += x1; x1 = (x1 << (R)) | (x1 >> (32-(R))); x1 ^= x0; }
  TFRND(13) TFRND(15) TFRND(26) TFRND(6)
  x0 += k1; x1 += k2 + 1u;
  TFRND(17) TFRND(29) TFRND(16) TFRND(24)
  x0 += k2; x1 += k0 + 2u;
  TFRND(13) TFRND(15) TFRND(26) TFRND(6)
  x0 += k0; x1 += k1 + 3u;
  TFRND(17) TFRND(29) TFRND(16) TFRND(24)
  x0 += k1; x1 += k2 + 4u;
  TFRND(13) TFRND(15) TFRND(26) TFRND(6)
  x0 += k2; x1 += k0 + 5u;
#undef TFRND
  return make_uint2(x0, x1);
}

// ---------------- accurate logf (~1 ulp; immune to fast-math) ----------------
__device__ __forceinline__ float acc_logf(float x){
  unsigned ix = __float_as_uint(x);
  unsigned off = ix + (0x3f800000u - 0x3f3504f3u);
  int k = ((int)(off >> 23)) - 127;
  unsigned mx = (off & 0x007fffffu) + 0x3f3504f3u;
  float f = __uint_as_float(mx) - 1.0f;
  float z = f * f;
  float p =              7.0376836292e-2f;
  p = fmaf(p, f, -1.1514610310e-1f);
  p = fmaf(p, f,  1.1676998740e-1f);
  p = fmaf(p, f, -1.2420140846e-1f);
  p = fmaf(p, f,  1.4249322787e-1f);
  p = fmaf(p, f, -1.6668057665e-1f);
  p = fmaf(p, f,  2.0000714765e-1f);
  p = fmaf(p, f, -2.4999993993e-1f);
  p = fmaf(p, f,  3.3333331174e-1f);
  float y = f * z * p;
  y = fmaf(-0.5f, z, y);
  float r = fmaf((float)k, -2.12194440e-4f, y);
  r = f + r;
  r = fmaf((float)k, 0.693359375f, r);
  return r;
}

__device__ __forceinline__ float gumbel_bits(unsigned bits){
  float f = __uint_as_float((bits >> 9) | 0x3f800000u) - 1.0f;
  float u = fmaxf(f, 1.17549435e-38f);
  float t = -acc_logf(u);
  return -acc_logf(t);
}

// ---------------- packed f32x2 helpers ----------------
__device__ __forceinline__ void fma2(unsigned long long &acc, unsigned long long a, unsigned long long b){
  asm("fma.rn.f32x2 %0, %1, %2, %0;" : "+l"(acc) : "l"(a), "l"(b));
}
__device__ __forceinline__ unsigned long long pack2(float x, float y){
  unsigned long long r; asm("mov.b64 %0, {%1, %2};" : "=l"(r) : "f"(x), "f"(y)); return r;
}
__device__ __forceinline__ float2 unpack2(unsigned long long v){
  float2 r; asm("mov.b64 {%0, %1}, %2;" : "=f"(r.x), "=f"(r.y) : "l"(v)); return r;
}

// combined logit (IDENTICAL expression everywhere)
__device__ __forceinline__ float comb_logit(float p0, float p1, float p2, float p3, float bv){
  return ((p0 + p1) + (p2 + p3)) + bv;
}

// ---------------- init ----------------
__global__ void init_kernel(const float* __restrict__ encoded){
  int gid = blockIdx.x * blockDim.x + threadIdx.x;
  d_x[gid] = encoded[gid];
  d_h[gid] = 0.f;
  d_c[gid] = 0.f;
  if (gid < BB) d_act[0][gid] = 1;
  if (gid < SS) d_keys[gid] = tf2x32(0u, 42u, 0u, (unsigned)gid);
}

// ---------------- gates: [B,4H] = x@Wi^T + h@Wh^T + bias ----------------
__global__ void __launch_bounds__(128) gates_kernel(const float* __restrict__ Wi,
                                                    const float* __restrict__ Wh,
                                                    const float* __restrict__ bi,
                                                    const float* __restrict__ bh){
  __shared__ ulonglong2 sx2[EE];
  __shared__ ulonglong2 sh2[HH];
  int b0 = blockIdx.y * 4;
  for (int i = threadIdx.x; i < EE; i += 128){
    ulonglong2 vx, vh;
    vx.x = pack2(d_x[(b0+0)*EE + i], d_x[(b0+1)*EE + i]);
    vx.y = pack2(d_x[(b0+2)*EE + i], d_x[(b0+3)*EE + i]);
    vh.x = pack2(d_h[(b0+0)*HH + i], d_h[(b0+1)*HH + i]);
    vh.y = pack2(d_h[(b0+2)*HH + i], d_h[(b0+3)*HH + i]);
    sx2[i] = vx; sh2[i] = vh;
  }
  __syncthreads();

  int j = blockIdx.x * 128 + threadIdx.x;
  const float4* wi = reinterpret_cast<const float4*>(Wi + (size_t)j * EE);
  const float4* wh = reinterpret_cast<const float4*>(Wh + (size_t)j * HH);
  unsigned long long ax0 = 0ull, ax1 = 0ull, ah0 = 0ull, ah1 = 0ull;
#pragma unroll 2
  for (int kq = 0; kq < EE/4; ++kq){
    float4 a = __ldg(wi + kq);
    float4 b = __ldg(wh + kq);
#pragma unroll
    for (int kk = 0; kk < 4; ++kk){
      ulonglong2 xv = sx2[kq*4 + kk];
      ulonglong2 hv = sh2[kq*4 + kk];
      float wa = (&a.x)[kk], wb = (&b.x)[kk];
      unsigned long long pa = pack2(wa, wa);
      unsigned long long pb = pack2(wb, wb);
      fma2(ax0, pa, xv.x); fma2(ax1, pa, xv.y);
      fma2(ah0, pb, hv.x); fma2(ah1, pb, hv.y);
    }
  }
  float bias = bi[j] + bh[j];
  float2 x0 = unpack2(ax0), x1 = unpack2(ax1);
  float2 h0 = unpack2(ah0), h1 = unpack2(ah1);
  d_gates[(b0+0)*GG + j] = x0.x + h0.x + bias;
  d_gates[(b0+1)*GG + j] = x0.y + h0.y + bias;
  d_gates[(b0+2)*GG + j] = x1.x + h1.x + bias;
  d_gates[(b0+3)*GG + j] = x1.y + h1.y + bias;
}

// ---------------- LSTM cell + pair-major transposed h write ----------------
__global__ void cell_kernel(){
  int b = blockIdx.x, k = threadIdx.x;
  float ig = d_gates[b*GG + k];
  float fg = d_gates[b*GG + 512 + k];
  float gg = d_gates[b*GG + 1024 + k];
  float og = d_gates[b*GG + 1536 + k];
  ig = 1.f / (1.f + expf(-ig));
  fg = 1.f / (1.f + expf(-fg));
  og = 1.f / (1.f + expf(-og));
  gg = tanhf(gg);
  float c = fg * d_c[b*HH + k] + ig * gg;
  d_c[b*HH + k] = c;
  float hval = og * tanhf(c);
  d_h[b*HH + k] = hval;
  reinterpret_cast<unsigned*>(d_h2)[(k*16 + (b>>1))*2 + (b&1)] = __float_as_uint(hval);
}

// ---------------- vocab logits, split into 4 K-quarters ----------------
// grid (63 rowblocks, 4 kquarters) x 256 threads, 2 blocks/SM.
// Thread: 2 vocab rows (r0, r0+256) x 32 batches, 128 k values.
__global__ void __launch_bounds__(256, 2) logits_kernel(const float* __restrict__ Wo){
  __shared__ unsigned long long h2[128*16];           // 16 KB: this k-quarter, pair-major
  int kq4 = blockIdx.y;
  {
    const ulonglong2* src = reinterpret_cast<const ulonglong2*>(d_h2 + kq4*128*16);
    ulonglong2* dst = reinterpret_cast<ulonglong2*>(h2);
    for (int i = threadIdx.x; i < 128*8; i += 256) dst[i] = src[i];
  }
  __syncthreads();

  int base = blockIdx.x * 512;
  int r0 = base + threadIdx.x;
  int r1 = base + 256 + threadIdx.x;
  bool v1 = (r1 < VV);
  const float4* w0 = reinterpret_cast<const float4*>(Wo + (size_t)r0 * HH + kq4*128);
  const float4* w1 = reinterpret_cast<const float4*>(Wo + (size_t)(v1 ? r1 : r0) * HH + kq4*128);

  unsigned long long acc0[16], acc1[16];
#pragma unroll
  for (int p = 0; p < 16; ++p){ acc0[p] = 0ull; acc1[p] = 0ull; }

  float4 a = __ldg(w0);
  float4 b = __ldg(w1);
#pragma unroll 1
  for (int kq = 0; kq < 32; ++kq){
    float4 ca = a, cb = b;
    if (kq < 31){ a = __ldg(w0 + kq + 1); b = __ldg(w1 + kq + 1); }
#pragma unroll
    for (int kk = 0; kk < 4; ++kk){
      const ulonglong2* hp = reinterpret_cast<const ulonglong2*>(h2) + (kq*4 + kk)*8;
      ulonglong2 v0_ = hp[0], v1_ = hp[1], v2_ = hp[2], v3_ = hp[3];
      ulonglong2 v4_ = hp[4], v5_ = hp[5], v6_ = hp[6], v7_ = hp[7];
      float wa = (&ca.x)[kk], wb = (&cb.x)[kk];
      unsigned long long pa = pack2(wa, wa);
      unsigned long long pb = pack2(wb, wb);
      fma2(acc0[0],  pa, v0_.x); fma2(acc0[1],  pa, v0_.y);
      fma2(acc0[2],  pa, v1_.x); fma2(acc0[3],  pa, v1_.y);
      fma2(acc0[4],  pa, v2_.x); fma2(acc0[5],  pa, v2_.y);
      fma2(acc0[6],  pa, v3_.x); fma2(acc0[7],  pa, v3_.y);
      fma2(acc0[8],  pa, v4_.x); fma2(acc0[9],  pa, v4_.y);
      fma2(acc0[10], pa, v5_.x); fma2(acc0[11], pa, v5_.y);
      fma2(acc0[12], pa, v6_.x); fma2(acc0[13], pa, v6_.y);
      fma2(acc0[14], pa, v7_.x); fma2(acc0[15], pa, v7_.y);
      fma2(acc1[0],  pb, v0_.x); fma2(acc1[1],  pb, v0_.y);
      fma2(acc1[2],  pb, v1_.x); fma2(acc1[3],  pb, v1_.y);
      fma2(acc1[4],  pb, v2_.x); fma2(acc1[5],  pb, v2_.y);
      fma2(acc1[6],  pb, v3_.x); fma2(acc1[7],  pb, v3_.y);
      fma2(acc1[8],  pb, v4_.x); fma2(acc1[9],  pb, v4_.y);
      fma2(acc1[10], pb, v5_.x); fma2(acc1[11], pb, v5_.y);
      fma2(acc1[12], pb, v6_.x); fma2(acc1[13], pb, v6_.y);
      fma2(acc1[14], pb, v7_.x); fma2(acc1[15], pb, v7_.y);
    }
  }

  float* dst = d_part[kq4];
#pragma unroll
  for (int p = 0; p < 16; ++p){
    float2 u0 = unpack2(acc0[p]);
    dst[(size_t)(2*p)  *VV + r0] = u0.x;
    dst[(size_t)(2*p+1)*VV + r0] = u0.y;
  }
  if (v1){
#pragma unroll
    for (int p = 0; p < 16; ++p){
      float2 u1 = unpack2(acc1[p]);
      dst[(size_t)(2*p)  *VV + r1] = u1.x;
      dst[(size_t)(2*p+1)*VV + r1] = u1.y;
    }
  }
}

// ---------------- gumbel: combine partials -> d_logits, + argmax + sum(exp) partials ----------------
// grid (16 slices, 32 batches) x 256 threads; slice = 2000 vocab entries.
__global__ void gumbel_kernel(int step, const float* __restrict__ bo){
  __shared__ float sv[256];
  __shared__ int   si[256];
  __shared__ float ss[256];
  int slice = blockIdx.x, b = blockIdx.y, tid = threadIdx.x;
  uint2 key = d_keys[step];
  float bm = -3.402823466e38f; int bidx = 0x7fffffff;
  float sum = 0.f;
  int v0 = slice * 2000;
  for (int v = v0 + tid; v < v0 + 2000; v += 256){
    float lg = comb_logit(d_part[0][b*VV + v], d_part[1][b*VV + v],
                          d_part[2][b*VV + v], d_part[3][b*VV + v], __ldg(bo + v));
    d_logits[b*VV + v] = lg;
    sum += expf(lg);
    uint2 r = tf2x32(key.x, key.y, 0u, (unsigned)(b*VV + v));
    float sc = lg + gumbel_bits(r.x ^ r.y);
    if (sc > bm || (sc == bm && v < bidx)){ bm = sc; bidx = v; }
  }
  sv[tid] = bm; si[tid] = bidx; ss[tid] = sum; __syncthreads();
  for (int o = 128; o > 0; o >>= 1){
    if (tid < o){
      float ov = sv[tid+o]; int oi = si[tid+o];
      if (ov > sv[tid] || (ov == sv[tid] && oi < si[tid])){ sv[tid] = ov; si[tid] = oi; }
      ss[tid] += ss[tid+o];
    }
    __syncthreads();
  }
  if (tid == 0){
    d_pval[b*NSLICE + slice] = sv[0];
    d_pidx[b*NSLICE + slice] = si[0];
    d_psum[b*NSLICE + slice] = ss[0];
  }
}

// ---------------- store_fin: grid (9 slices, 32 batches) x 256 ----------------
// slices 0..7: masked logp store (rs recomputed redundantly, identical fp order).
// slice 8: token argmax, EOS -> d_act[p^1], embed gather -> d_x.
__global__ void store_fin_kernel(float* __restrict__ out, int step,
                                 const float* __restrict__ emb){
  int slice = blockIdx.x, b = blockIdx.y, tid = threadIdx.x;
  int par = step & 1;
  int act = d_act[par][b];

  if (slice < 8){
    float S = 0.f;
#pragma unroll
    for (int s2 = 0; s2 < NSLICE; ++s2) S += d_psum[b*NSLICE + s2];
    float rs = acc_logf(S);
    const float4* row = reinterpret_cast<const float4*>(d_logits + b*VV);
    float4* orow = reinterpret_cast<float4*>(out + ((size_t)b * SS + step) * VV);
    int q0 = slice * 1000;                  // 1000 float4 per slice
    for (int v = q0 + tid; v < q0 + 1000; v += 256){
      float4 x = row[v];
      float4 o4;
      o4.x = act ? x.x - rs : 0.0f;
      o4.y = act ? x.y - rs : 0.0f;
      o4.z = act ? x.z - rs : 0.0f;
      o4.w = act ? x.w - rs : 0.0f;
      orow[v] = o4;
    }
  } else {
    __shared__ int stok;
    if (tid == 0){
      float bm = d_pval[b*NSLICE]; int bi_ = d_pidx[b*NSLICE];
#pragma unroll
      for (int s2 = 1; s2 < NSLICE; ++s2){
        float v = d_pval[b*NSLICE + s2]; int i2 = d_pidx[b*NSLICE + s2];
        if (v > bm || (v == bm && i2 < bi_)){ bm = v; bi_ = i2; }
      }
      stok = bi_;
      d_act[par^1][b] = act && (bi_ != VV - 2);   // EOS for NEXT step
    }
    __syncthreads();
    int t = stok;
    d_x[b*EE + tid]       = emb[(size_t)t*EE + tid];
    d_x[b*EE + 256 + tid] = emb[(size_t)t*EE + 256 + tid];
  }
}

// ---------------- launch ----------------
extern "C" void kernel_launch(void* const* d_in, const int* in_sizes, int n_in,
                              void* d_out, int out_size){
  const float* encoded = (const float*)d_in[0];
  const float* emb     = (const float*)d_in[1];
  const float* Wi      = (const float*)d_in[2];
  const float* Wh      = (const float*)d_in[3];
  const float* bi      = (const float*)d_in[4];
  const float* bh      = (const float*)d_in[5];
  const float* Wo      = (const float*)d_in[6];
  const float* bo      = (const float*)d_in[7];
  float* out = (float*)d_out;

  init_kernel<<<64, 256>>>(encoded);
  for (int s = 0; s < SS; ++s){
    gates_kernel<<<dim3(16, 8), 128>>>(Wi, Wh, bi, bh);
    cell_kernel<<<32, 512>>>();
    logits_kernel<<<dim3(63, 4), 256>>>(Wo);
    gumbel_kernel<<<dim3(NSLICE, 32), 256>>>(s, bo);
    store_fin_kernel<<<dim3(9, 32), 256>>>(out, s, emb);
  }
}

// round 9
// speedup vs baseline: 1.9446x; 1.0091x over previous
#include <cuda_runtime.h>
#include <cstdint>
#include <cstddef>

#define BB 32
#define SS 48
#define VV 32000
#define EE 512
#define HH 512
#define GG 2048
#define NSLICE 16

// ---------------- persistent device state ----------------
__device__ __align__(16) float d_x[BB*EE];
__device__ __align__(16) float d_h[BB*HH];
__device__ __align__(16) float d_c[BB*HH];
__device__ __align__(16) float d_gates[BB*GG];
__device__ __align__(16) float d_part[4][BB*VV];           // split-K partials (16 MB)
__device__ __align__(16) float d_logits[BB*VV];            // combined logits (gumbel output)
__device__ __align__(16) unsigned long long d_h2[HH*16];   // pair-major transposed h
__device__ float d_pval[BB*NSLICE];
__device__ int   d_pidx[BB*NSLICE];
__device__ float d_psum[BB*NSLICE];
__device__ int   d_act[2][BB];                             // ping-pong active flags
__device__ uint2 d_keys[SS];

// ---------------- threefry2x32 (exact JAX algorithm, 20 rounds) ----------------
__device__ __forceinline__ uint2 tf2x32(unsigned k0, unsigned k1, unsigned x0, unsigned x1){
  unsigned k2 = 0x1BD11BDAu ^ k0 ^ k1;
  x0 += k0; x1 += k1;
#define TFRND(R) { x0 += x1; x1 = (x1 << (R)) | (x1 >> (32-(R))); x1 ^= x0; }
  TFRND(13) TFRND(15) TFRND(26) TFRND(6)
  x0 += k1; x1 += k2 + 1u;
  TFRND(17) TFRND(29) TFRND(16) TFRND(24)
  x0 += k2; x1 += k0 + 2u;
  TFRND(13) TFRND(15) TFRND(26) TFRND(6)
  x0 += k0; x1 += k1 + 3u;
  TFRND(17) TFRND(29) TFRND(16) TFRND(24)
  x0 += k1; x1 += k2 + 4u;
  TFRND(13) TFRND(15) TFRND(26) TFRND(6)
  x0 += k2; x1 += k0 + 5u;
#undef TFRND
  return make_uint2(x0, x1);
}

// ---------------- accurate logf (~1 ulp; immune to fast-math) ----------------
__device__ __forceinline__ float acc_logf(float x){
  unsigned ix = __float_as_uint(x);
  unsigned off = ix + (0x3f800000u - 0x3f3504f3u);
  int k = ((int)(off >> 23)) - 127;
  unsigned mx = (off & 0x007fffffu) + 0x3f3504f3u;
  float f = __uint_as_float(mx) - 1.0f;
  float z = f * f;
  float p =              7.0376836292e-2f;
  p = fmaf(p, f, -1.1514610310e-1f);
  p = fmaf(p, f,  1.1676998740e-1f);
  p = fmaf(p, f, -1.2420140846e-1f);
  p = fmaf(p, f,  1.4249322787e-1f);
  p = fmaf(p, f, -1.6668057665e-1f);
  p = fmaf(p, f,  2.0000714765e-1f);
  p = fmaf(p, f, -2.4999993993e-1f);
  p = fmaf(p, f,  3.3333331174e-1f);
  float y = f * z * p;
  y = fmaf(-0.5f, z, y);
  float r = fmaf((float)k, -2.12194440e-4f, y);
  r = f + r;
  r = fmaf((float)k, 0.693359375f, r);
  return r;
}

__device__ __forceinline__ float gumbel_bits(unsigned bits){
  float f = __uint_as_float((bits >> 9) | 0x3f800000u) - 1.0f;
  float u = fmaxf(f, 1.17549435e-38f);
  float t = -acc_logf(u);
  return -acc_logf(t);
}

// ---------------- packed f32x2 helpers ----------------
__device__ __forceinline__ void fma2(unsigned long long &acc, unsigned long long a, unsigned long long b){
  asm("fma.rn.f32x2 %0, %1, %2, %0;" : "+l"(acc) : "l"(a), "l"(b));
}
__device__ __forceinline__ unsigned long long pack2(float x, float y){
  unsigned long long r; asm("mov.b64 %0, {%1, %2};" : "=l"(r) : "f"(x), "f"(y)); return r;
}
__device__ __forceinline__ float2 unpack2(unsigned long long v){
  float2 r; asm("mov.b64 {%0, %1}, %2;" : "=f"(r.x), "=f"(r.y) : "l"(v)); return r;
}

// combined logit (IDENTICAL expression everywhere)
__device__ __forceinline__ float comb_logit(float p0, float p1, float p2, float p3, float bv){
  return ((p0 + p1) + (p2 + p3)) + bv;
}

// ---------------- init ----------------
__global__ void init_kernel(const float* __restrict__ encoded){
  int gid = blockIdx.x * blockDim.x + threadIdx.x;
  d_x[gid] = encoded[gid];
  d_h[gid] = 0.f;
  d_c[gid] = 0.f;
  if (gid < BB) d_act[0][gid] = 1;
  if (gid < SS) d_keys[gid] = tf2x32(0u, 42u, 0u, (unsigned)gid);
}

// ---------------- gates: [B,4H] = x@Wi^T + h@Wh^T + bias ----------------
__global__ void __launch_bounds__(128) gates_kernel(const float* __restrict__ Wi,
                                                    const float* __restrict__ Wh,
                                                    const float* __restrict__ bi,
                                                    const float* __restrict__ bh){
  __shared__ ulonglong2 sx2[EE];
  __shared__ ulonglong2 sh2[HH];
  int b0 = blockIdx.y * 4;
  for (int i = threadIdx.x; i < EE; i += 128){
    ulonglong2 vx, vh;
    vx.x = pack2(d_x[(b0+0)*EE + i], d_x[(b0+1)*EE + i]);
    vx.y = pack2(d_x[(b0+2)*EE + i], d_x[(b0+3)*EE + i]);
    vh.x = pack2(d_h[(b0+0)*HH + i], d_h[(b0+1)*HH + i]);
    vh.y = pack2(d_h[(b0+2)*HH + i], d_h[(b0+3)*HH + i]);
    sx2[i] = vx; sh2[i] = vh;
  }
  __syncthreads();

  int j = blockIdx.x * 128 + threadIdx.x;
  const float4* wi = reinterpret_cast<const float4*>(Wi + (size_t)j * EE);
  const float4* wh = reinterpret_cast<const float4*>(Wh + (size_t)j * HH);
  unsigned long long ax0 = 0ull, ax1 = 0ull, ah0 = 0ull, ah1 = 0ull;
#pragma unroll 2
  for (int kq = 0; kq < EE/4; ++kq){
    float4 a = __ldg(wi + kq);
    float4 b = __ldg(wh + kq);
#pragma unroll
    for (int kk = 0; kk < 4; ++kk){
      ulonglong2 xv = sx2[kq*4 + kk];
      ulonglong2 hv = sh2[kq*4 + kk];
      float wa = (&a.x)[kk], wb = (&b.x)[kk];
      unsigned long long pa = pack2(wa, wa);
      unsigned long long pb = pack2(wb, wb);
      fma2(ax0, pa, xv.x); fma2(ax1, pa, xv.y);
      fma2(ah0, pb, hv.x); fma2(ah1, pb, hv.y);
    }
  }
  float bias = bi[j] + bh[j];
  float2 x0 = unpack2(ax0), x1 = unpack2(ax1);
  float2 h0 = unpack2(ah0), h1 = unpack2(ah1);
  d_gates[(b0+0)*GG + j] = x0.x + h0.x + bias;
  d_gates[(b0+1)*GG + j] = x0.y + h0.y + bias;
  d_gates[(b0+2)*GG + j] = x1.x + h1.x + bias;
  d_gates[(b0+3)*GG + j] = x1.y + h1.y + bias;
}

// ---------------- LSTM cell + pair-major transposed h write ----------------
__global__ void cell_kernel(){
  int b = blockIdx.x, k = threadIdx.x;
  float ig = d_gates[b*GG + k];
  float fg = d_gates[b*GG + 512 + k];
  float gg = d_gates[b*GG + 1024 + k];
  float og = d_gates[b*GG + 1536 + k];
  ig = 1.f / (1.f + expf(-ig));
  fg = 1.f / (1.f + expf(-fg));
  og = 1.f / (1.f + expf(-og));
  gg = tanhf(gg);
  float c = fg * d_c[b*HH + k] + ig * gg;
  d_c[b*HH + k] = c;
  float hval = og * tanhf(c);
  d_h[b*HH + k] = hval;
  reinterpret_cast<unsigned*>(d_h2)[(k*16 + (b>>1))*2 + (b&1)] = __float_as_uint(hval);
}

// ---------------- vocab logits, split into 4 K-quarters ----------------
// grid (63 rowblocks, 4 kquarters) x 256 threads, 2 blocks/SM.
// Thread: 2 vocab rows (r0, r0+256) x 32 batches, 128 k values.
__global__ void __launch_bounds__(256, 2) logits_kernel(const float* __restrict__ Wo){
  __shared__ unsigned long long h2[128*16];           // 16 KB: this k-quarter, pair-major
  int kq4 = blockIdx.y;
  {
    const ulonglong2* src = reinterpret_cast<const ulonglong2*>(d_h2 + kq4*128*16);
    ulonglong2* dst = reinterpret_cast<ulonglong2*>(h2);
    for (int i = threadIdx.x; i < 128*8; i += 256) dst[i] = src[i];
  }
  __syncthreads();

  int base = blockIdx.x * 512;
  int r0 = base + threadIdx.x;
  int r1 = base + 256 + threadIdx.x;
  bool v1 = (r1 < VV);
  const float4* w0 = reinterpret_cast<const float4*>(Wo + (size_t)r0 * HH + kq4*128);
  const float4* w1 = reinterpret_cast<const float4*>(Wo + (size_t)(v1 ? r1 : r0) * HH + kq4*128);

  unsigned long long acc0[16], acc1[16];
#pragma unroll
  for (int p = 0; p < 16; ++p){ acc0[p] = 0ull; acc1[p] = 0ull; }

  float4 a = __ldg(w0);
  float4 b = __ldg(w1);
#pragma unroll 1
  for (int kq = 0; kq < 32; ++kq){
    float4 ca = a, cb = b;
    if (kq < 31){ a = __ldg(w0 + kq + 1); b = __ldg(w1 + kq + 1); }
#pragma unroll
    for (int kk = 0; kk < 4; ++kk){
      const ulonglong2* hp = reinterpret_cast<const ulonglong2*>(h2) + (kq*4 + kk)*8;
      ulonglong2 v0_ = hp[0], v1_ = hp[1], v2_ = hp[2], v3_ = hp[3];
      ulonglong2 v4_ = hp[4], v5_ = hp[5], v6_ = hp[6], v7_ = hp[7];
      float wa = (&ca.x)[kk], wb = (&cb.x)[kk];
      unsigned long long pa = pack2(wa, wa);
      unsigned long long pb = pack2(wb, wb);
      fma2(acc0[0],  pa, v0_.x); fma2(acc0[1],  pa, v0_.y);
      fma2(acc0[2],  pa, v1_.x); fma2(acc0[3],  pa, v1_.y);
      fma2(acc0[4],  pa, v2_.x); fma2(acc0[5],  pa, v2_.y);
      fma2(acc0[6],  pa, v3_.x); fma2(acc0[7],  pa, v3_.y);
      fma2(acc0[8],  pa, v4_.x); fma2(acc0[9],  pa, v4_.y);
      fma2(acc0[10], pa, v5_.x); fma2(acc0[11], pa, v5_.y);
      fma2(acc0[12], pa, v6_.x); fma2(acc0[13], pa, v6_.y);
      fma2(acc0[14], pa, v7_.x); fma2(acc0[15], pa, v7_.y);
      fma2(acc1[0],  pb, v0_.x); fma2(acc1[1],  pb, v0_.y);
      fma2(acc1[2],  pb, v1_.x); fma2(acc1[3],  pb, v1_.y);
      fma2(acc1[4],  pb, v2_.x); fma2(acc1[5],  pb, v2_.y);
      fma2(acc1[6],  pb, v3_.x); fma2(acc1[7],  pb, v3_.y);
      fma2(acc1[8],  pb, v4_.x); fma2(acc1[9],  pb, v4_.y);
      fma2(acc1[10], pb, v5_.x); fma2(acc1[11], pb, v5_.y);
      fma2(acc1[12], pb, v6_.x); fma2(acc1[13], pb, v6_.y);
      fma2(acc1[14], pb, v7_.x); fma2(acc1[15], pb, v7_.y);
    }
  }

  float* dst = d_part[kq4];
#pragma unroll
  for (int p = 0; p < 16; ++p){
    float2 u0 = unpack2(acc0[p]);
    dst[(size_t)(2*p)  *VV + r0] = u0.x;
    dst[(size_t)(2*p+1)*VV + r0] = u0.y;
  }
  if (v1){
#pragma unroll
    for (int p = 0; p < 16; ++p){
      float2 u1 = unpack2(acc1[p]);
      dst[(size_t)(2*p)  *VV + r1] = u1.x;
      dst[(size_t)(2*p+1)*VV + r1] = u1.y;
    }
  }
}

// ---------------- gumbel: combine partials -> d_logits, + argmax + sum(exp) partials ----------------
// grid (16 slices, 32 batches) x 256 threads; slice = 2000 vocab entries.
__global__ void gumbel_kernel(int step, const float* __restrict__ bo){
  __shared__ float sv[256];
  __shared__ int   si[256];
  __shared__ float ss[256];
  int slice = blockIdx.x, b = blockIdx.y, tid = threadIdx.x;
  uint2 key = d_keys[step];
  float bm = -3.402823466e38f; int bidx = 0x7fffffff;
  float sum = 0.f;
  int v0 = slice * 2000;
  for (int v = v0 + tid; v < v0 + 2000; v += 256){
    float lg = comb_logit(d_part[0][b*VV + v], d_part[1][b*VV + v],
                          d_part[2][b*VV + v], d_part[3][b*VV + v], __ldg(bo + v));
    d_logits[b*VV + v] = lg;
    sum += expf(lg);
    uint2 r = tf2x32(key.x, key.y, 0u, (unsigned)(b*VV + v));
    float sc = lg + gumbel_bits(r.x ^ r.y);
    if (sc > bm || (sc == bm && v < bidx)){ bm = sc; bidx = v; }
  }
  sv[tid] = bm; si[tid] = bidx; ss[tid] = sum; __syncthreads();
  for (int o = 128; o > 0; o >>= 1){
    if (tid < o){
      float ov = sv[tid+o]; int oi = si[tid+o];
      if (ov > sv[tid] || (ov == sv[tid] && oi < si[tid])){ sv[tid] = ov; si[tid] = oi; }
      ss[tid] += ss[tid+o];
    }
    __syncthreads();
  }
  if (tid == 0){
    d_pval[b*NSLICE + slice] = sv[0];
    d_pidx[b*NSLICE + slice] = si[0];
    d_psum[b*NSLICE + slice] = ss[0];
  }
}

// ---------------- store_fin: grid (9 slices, 32 batches) x 256 ----------------
// slices 0..7: masked logp store (rs recomputed redundantly, identical fp order).
// slice 8: token argmax, EOS -> d_act[p^1], embed gather -> d_x.
__global__ void store_fin_kernel(float* __restrict__ out, int step,
                                 const float* __restrict__ emb){
  int slice = blockIdx.x, b = blockIdx.y, tid = threadIdx.x;
  int par = step & 1;
  int act = d_act[par][b];

  if (slice < 8){
    float S = 0.f;
#pragma unroll
    for (int s2 = 0; s2 < NSLICE; ++s2) S += d_psum[b*NSLICE + s2];
    float rs = acc_logf(S);
    const float4* row = reinterpret_cast<const float4*>(d_logits + b*VV);
    float4* orow = reinterpret_cast<float4*>(out + ((size_t)b * SS + step) * VV);
    int q0 = slice * 1000;                  // 1000 float4 per slice
    for (int v = q0 + tid; v < q0 + 1000; v += 256){
      float4 x = row[v];
      float4 o4;
      o4.x = act ? x.x - rs : 0.0f;
      o4.y = act ? x.y - rs : 0.0f;
      o4.z = act ? x.z - rs : 0.0f;
      o4.w = act ? x.w - rs : 0.0f;
      orow[v] = o4;
    }
  } else {
    __shared__ int stok;
    if (tid == 0){
      float bm = d_pval[b*NSLICE]; int bi_ = d_pidx[b*NSLICE];
#pragma unroll
      for (int s2 = 1; s2 < NSLICE; ++s2){
        float v = d_pval[b*NSLICE + s2]; int i2 = d_pidx[b*NSLICE + s2];
        if (v > bm || (v == bm && i2 < bi_)){ bm = v; bi_ = i2; }
      }
      stok = bi_;
      d_act[par^1][b] = act && (bi_ != VV - 2);   // EOS for NEXT step
    }
    __syncthreads();
    int t = stok;
    d_x[b*EE + tid]       = emb[(size_t)t*EE + tid];
    d_x[b*EE + 256 + tid] = emb[(size_t)t*EE + 256 + tid];
  }
}

// ---------------- launch ----------------
extern "C" void kernel_launch(void* const* d_in, const int* in_sizes, int n_in,
                              void* d_out, int out_size){
  const float* encoded = (const float*)d_in[0];
  const float* emb     = (const float*)d_in[1];
  const float* Wi      = (const float*)d_in[2];
  const float* Wh      = (const float*)d_in[3];
  const float* bi      = (const float*)d_in[4];
  const float* bh      = (const float*)d_in[5];
  const float* Wo      = (const float*)d_in[6];
  const float* bo      = (const float*)d_in[7];
  float* out = (float*)d_out;

  init_kernel<<<64, 256>>>(encoded);
  for (int s = 0; s < SS; ++s){
    gates_kernel<<<dim3(16, 8), 128>>>(Wi, Wh, bi, bh);
    cell_kernel<<<32, 512>>>();
    logits_kernel<<<dim3(63, 4), 256>>>(Wo);
    gumbel_kernel<<<dim3(NSLICE, 32), 256>>>(s, bo);
    store_fin_kernel<<<dim3(9, 32), 256>>>(out, s, emb);
  }
}